// round 5
// baseline (speedup 1.0000x reference)
#include <cuda_runtime.h>

// ---------------- problem constants ----------------
#define NTOT 4096      // B*n nodes
#define HDIM 128
#define NBAT 64
#define NEDG 131072    // given edges (self loops appended logically)
#define KSEL 52        // ceil(0.8*64)
#define NKEEP 3328     // 64*52

// output layout (float32 flat): x_out, A2, batch_out, perm
#define O_A2   425984LL
#define O_BAT  11501568LL
#define O_PERM 11504896LL

// scratch offsets (floats)
#define OFF_A     0LL
#define OFF_H0    524288LL
#define OFF_H1    2621440LL
#define OFF_H2    3670016LL
#define OFF_XQ    4194304LL
#define OFF_TMP   4718592LL
#define OFF_TMP2  5242880LL
#define OFF_AGG   5767168LL
#define OFF_XC    6291456LL
#define OFF_AW    6815744LL
#define OFF_CNT   7077888LL
#define OFF_DEG   7340032LL
#define OFF_DINV  7344128LL
#define OFF_S     7348224LL
#define OFF_F     7610368LL
#define OFF_SCORE 7626752LL
#define OFF_PERM  7630848LL
#define SCRATCH_TOTAL 7634176LL

__device__ float g_scratch[SCRATCH_TOTAL];

__device__ __forceinline__ float lrelu(float v) { return v >= 0.f ? v : 0.01f * v; }

// ---------------- generic zero ----------------
__global__ void k_zero(float* p, int n) {
    int i = blockIdx.x * 256 + threadIdx.x;
    if (i < n) p[i] = 0.f;
}

// ---------------- degree ----------------
__global__ void k_deg(const int* __restrict__ ei, const float* __restrict__ w,
                      float* __restrict__ deg) {
    int e = blockIdx.x * 256 + threadIdx.x;
    if (e < NEDG) atomicAdd(&deg[ei[NEDG + e]], w[e]);          // col-indexed
    else if (e < NEDG + NTOT) atomicAdd(&deg[e - NEDG], 1.0f);  // self loop
}

__global__ void k_dinv(const float* __restrict__ deg, float* __restrict__ dinv) {
    int i = blockIdx.x * 256 + threadIdx.x;
    if (i < NTOT) {
        float d = deg[i];
        dinv[i] = d > 0.f ? rsqrtf(fmaxf(d, 1e-12f)) : 0.f;
    }
}

// ---------------- dense per-batch adjacency (Aw = sum ew, cnt = multiplicity) --------
__global__ void k_adj(const int* __restrict__ ei, const float* __restrict__ w,
                      const float* __restrict__ dinv,
                      float* __restrict__ Aw, float* __restrict__ cnt) {
    int e = blockIdx.x * 256 + threadIdx.x;
    int r, c; float wv;
    if (e < NEDG)            { r = ei[e]; c = ei[NEDG + e]; wv = w[e]; }
    else if (e < NEDG + NTOT){ r = c = e - NEDG; wv = 1.f; }
    else return;
    float evw = dinv[r] * wv * dinv[c];
    size_t o = (size_t)(r >> 6) * 4096 + (size_t)(r & 63) * 64 + (c & 63);
    atomicAdd(&Aw[o], evw);
    atomicAdd(&cnt[o], 1.f);
}

// ---------------- per-batch out = M_b^T @ v_b  (64x64 @ 64x128) ----------------
__global__ void k_bgemmT(const float* __restrict__ M, const float* __restrict__ vin,
                         float* __restrict__ vout) {
    __shared__ float Ms[64][64];
    __shared__ float vs[64][128];
    int b = blockIdx.x, tid = threadIdx.x;
    const float* Mb = M + (size_t)b * 4096;
    const float* vb = vin + (size_t)b * 8192;
    for (int i = tid; i < 4096; i += 256) Ms[i >> 6][i & 63] = Mb[i];
    float4* vs4 = (float4*)vs;
    const float4* vb4 = (const float4*)vb;
    for (int i = tid; i < 2048; i += 256) vs4[i] = vb4[i];
    __syncthreads();
    int tx = tid & 31, ty = tid >> 5;
    for (int c = ty; c < 64; c += 8) {
        float4 acc = make_float4(0.f, 0.f, 0.f, 0.f);
        #pragma unroll 8
        for (int r = 0; r < 64; r++) {
            float m = Ms[r][c];
            float4 v = *(float4*)&vs[r][tx * 4];
            acc.x += m * v.x; acc.y += m * v.y; acc.z += m * v.z; acc.w += m * v.w;
        }
        *(float4*)(vout + (size_t)(b * 64 + c) * 128 + tx * 4) = acc;
    }
}

// ---------------- tiled fp32 GEMM: C[N x MO] = act(A[N x K] @ W[K x MO]) -------------
__global__ void k_gemm(const float* __restrict__ A, const float* __restrict__ W,
                       float* __restrict__ C, int K, int MO, int leaky) {
    __shared__ float As[16][68];
    __shared__ float Ws[16][68];
    int tid = threadIdx.x;
    int m0 = blockIdx.x * 64, n0 = blockIdx.y * 64;
    int lr = tid >> 2, lk = (tid & 3) * 4;
    int wr = tid >> 4, wc = (tid & 15) * 4;
    int ty = tid >> 4, tx = tid & 15;
    float acc[4][4];
    #pragma unroll
    for (int i = 0; i < 4; i++)
        #pragma unroll
        for (int j = 0; j < 4; j++) acc[i][j] = 0.f;

    for (int k0 = 0; k0 < K; k0 += 16) {
        float4 av = *(const float4*)(A + (size_t)(m0 + lr) * K + k0 + lk);
        As[lk + 0][lr] = av.x; As[lk + 1][lr] = av.y;
        As[lk + 2][lr] = av.z; As[lk + 3][lr] = av.w;
        *(float4*)&Ws[wr][wc] = *(const float4*)(W + (size_t)(k0 + wr) * MO + n0 + wc);
        __syncthreads();
        #pragma unroll
        for (int kk = 0; kk < 16; kk++) {
            float4 a = *(float4*)&As[kk][ty * 4];
            float4 bvec = *(float4*)&Ws[kk][tx * 4];
            float aa[4] = {a.x, a.y, a.z, a.w};
            float bb[4] = {bvec.x, bvec.y, bvec.z, bvec.w};
            #pragma unroll
            for (int i = 0; i < 4; i++)
                #pragma unroll
                for (int j = 0; j < 4; j++) acc[i][j] += aa[i] * bb[j];
        }
        __syncthreads();
    }
    #pragma unroll
    for (int i = 0; i < 4; i++)
        #pragma unroll
        for (int j = 0; j < 4; j++) {
            float v = acc[i][j];
            if (leaky) v = lrelu(v);
            C[(size_t)(m0 + ty * 4 + i) * MO + n0 + tx * 4 + j] = v;
        }
}

// ---------------- h0 = [a, q, a-q, a*q] ----------------
__global__ void k_h0(const float* __restrict__ a, const float* __restrict__ q,
                     float* __restrict__ h0, int qtar) {
    int t = blockIdx.x * 256 + threadIdx.x;
    if (t >= NTOT * HDIM) return;
    int node = t >> 7, k = t & 127;
    float av = a[t];
    float qv = qtar ? q[(node >> 6) * HDIM + k] : q[t];
    float* h = h0 + (size_t)node * 512;
    h[k] = av; h[128 + k] = qv; h[256 + k] = av - qv; h[384 + k] = av * qv;
}

// ---------------- fused W3 dot + leaky + per-batch softmax ----------------
__global__ void k_fsm(const float* __restrict__ h2, const float* __restrict__ W3,
                      float* __restrict__ fout) {
    int b = blockIdx.x, t = threadIdx.x;   // 64 threads
    __shared__ float w3[128];
    __shared__ float red[64];
    w3[t] = W3[t]; w3[64 + t] = W3[64 + t];
    __syncthreads();
    int row = b * 64 + t;
    const float* h = h2 + (size_t)row * 128;
    float dot = 0.f;
    #pragma unroll 8
    for (int k = 0; k < 128; k++) dot += h[k] * w3[k];
    float v = lrelu(dot);
    red[t] = v; __syncthreads();
    for (int off = 32; off > 0; off >>= 1) {
        if (t < off) red[t] = fmaxf(red[t], red[t + off]);
        __syncthreads();
    }
    float m = red[0]; __syncthreads();
    float e = expf(v - m);
    red[t] = e; __syncthreads();
    for (int off = 32; off > 0; off >>= 1) {
        if (t < off) red[t] += red[t + off];
        __syncthreads();
    }
    fout[row] = e / red[0];
}

// ---------------- cluster score: softmax(g1+g2) per batch ----------------
__global__ void k_score(const float* __restrict__ g1, const float* __restrict__ g2,
                        float* __restrict__ score) {
    int b = blockIdx.x, t = threadIdx.x;
    __shared__ float red[64];
    int row = b * 64 + t;
    float v = g1[row] + g2[row];
    red[t] = v; __syncthreads();
    for (int off = 32; off > 0; off >>= 1) {
        if (t < off) red[t] = fmaxf(red[t], red[t + off]);
        __syncthreads();
    }
    float m = red[0]; __syncthreads();
    float e = expf(v - m);
    red[t] = e; __syncthreads();
    for (int off = 32; off > 0; off >>= 1) {
        if (t < off) red[t] += red[t + off];
        __syncthreads();
    }
    score[row] = e / red[0];
}

// ---------------- edge softmax -> dense S block  (thread = target column c) ---------
__global__ void k_sbuild(const float* __restrict__ f1, const float* __restrict__ f2,
                         const float* __restrict__ cnt, float* __restrict__ Sm) {
    int b = blockIdx.x, c = threadIdx.x;
    __shared__ float f2s[64];
    f2s[c] = f2[b * 64 + c];
    __syncthreads();
    float f1c = f1[b * 64 + c];
    const float* Cb = cnt + (size_t)b * 4096;
    float* Sb = Sm + (size_t)b * 4096;
    float m = -1e30f;
    for (int r = 0; r < 64; r++) m = fmaxf(m, lrelu(f1c + f2s[r]));  // shift-invariant
    float d = 0.f;
    for (int r = 0; r < 64; r++) {
        float val = lrelu(f1c + f2s[r]);
        float e = Cb[r * 64 + c] * expf(val - m);   // duplicates via cnt; cnt=0 -> 0
        Sb[r * 64 + c] = e; d += e;
    }
    float inv = 1.f / d;                            // self-loop guarantees d > 0
    for (int r = 0; r < 64; r++) Sb[r * 64 + c] *= inv;
}

// ---------------- x_c = mean over heads of leaky(x + agg@W_h) ----------------
__global__ void k_xc(const float* __restrict__ x, const float* __restrict__ t0,
                     const float* __restrict__ t1, float* __restrict__ xc) {
    int t = blockIdx.x * 256 + threadIdx.x;
    if (t >= NTOT * HDIM) return;
    float xv = x[t];
    xc[t] = 0.5f * (lrelu(xv + t0[t]) + lrelu(xv + t1[t]));
}

// ---------------- per-batch top-52 (descending, stable ties) ----------------
__global__ void k_topk(const float* __restrict__ score, int* __restrict__ perm) {
    int b = blockIdx.x, t = threadIdx.x;   // 64 threads
    __shared__ float s[64];
    __shared__ float rv[64];
    __shared__ int   ri[64];
    s[t] = score[b * 64 + t];
    __syncthreads();
    for (int j = 0; j < KSEL; j++) {
        rv[t] = s[t]; ri[t] = t; __syncthreads();
        for (int off = 32; off > 0; off >>= 1) {
            if (t < off) {
                float ov = rv[t + off]; int oi = ri[t + off];
                if (ov > rv[t] || (ov == rv[t] && oi < ri[t])) { rv[t] = ov; ri[t] = oi; }
            }
            __syncthreads();
        }
        if (t == 0) { perm[b * KSEL + j] = ri[0]; s[ri[0]] = -3.4e38f; }
        __syncthreads();
    }
}

// ---------------- outputs: x_out, batch_out, perm ----------------
__global__ void k_xout(const float* __restrict__ x, const float* __restrict__ score,
                       const int* __restrict__ perm, float* __restrict__ out) {
    int t = blockIdx.x * 256 + threadIdx.x;
    if (t >= NKEEP * HDIM) return;
    int j = t >> 7, k = t & 127;
    int b = j / KSEL;
    int pg = b * 64 + perm[j];
    out[t] = x[(size_t)pg * 128 + k] * score[pg];
    if (k == 0) {
        out[O_BAT + j]  = (float)b;
        out[O_PERM + j] = (float)pg;
    }
}

// ---------------- A2 diagonal block: Sp^T (Aw Sp), diag = 1 ----------------
__global__ void k_a2(const float* __restrict__ Aw, const float* __restrict__ Sm,
                     const int* __restrict__ perm, float* __restrict__ out) {
    int b = blockIdx.x, tid = threadIdx.x;   // 256 threads
    __shared__ float Aws[64][65];
    __shared__ float Sp[64][53];
    __shared__ float Ms[64][53];
    __shared__ int idx[52];
    const float* Ab = Aw + (size_t)b * 4096;
    for (int i = tid; i < 4096; i += 256) Aws[i >> 6][i & 63] = Ab[i];
    if (tid < 52) idx[tid] = perm[b * KSEL + tid];
    __syncthreads();
    const float* Sb = Sm + (size_t)b * 4096;
    for (int i = tid; i < 64 * 52; i += 256) {
        int r = i / 52, j = i % 52;
        Sp[r][j] = Sb[r * 64 + idx[j]];
    }
    __syncthreads();
    for (int i = tid; i < 64 * 52; i += 256) {
        int r = i / 52, j = i % 52;
        float acc = 0.f;
        #pragma unroll 8
        for (int c = 0; c < 64; c++) acc += Aws[r][c] * Sp[c][j];
        Ms[r][j] = acc;
    }
    __syncthreads();
    for (int i = tid; i < 52 * 52; i += 256) {
        int ii = i / 52, j = i % 52;
        float v;
        if (ii == j) v = 1.f;
        else {
            v = 0.f;
            #pragma unroll 8
            for (int r = 0; r < 64; r++) v += Sp[r][ii] * Ms[r][j];
        }
        long long gi = (long long)b * KSEL + ii;
        out[O_A2 + gi * NKEEP + b * KSEL + j] = v;
    }
}

// ---------------- host side ----------------
static void run_attn(int k, const float* kv, const float* q, int qtar,
                     const float* Wk, const float* W1, const float* W2, const float* W3,
                     float* sc, float* fout) {
    k_gemm<<<dim3(64, 2), 256>>>(kv, Wk + (size_t)k * 128 * 128, sc + OFF_A, 128, 128, 0);
    k_h0<<<(NTOT * HDIM) / 256, 256>>>(sc + OFF_A, q, sc + OFF_H0, qtar);
    k_gemm<<<dim3(64, 4), 256>>>(sc + OFF_H0, W1 + (size_t)k * 512 * 256, sc + OFF_H1, 512, 256, 1);
    k_gemm<<<dim3(64, 2), 256>>>(sc + OFF_H1, W2 + (size_t)k * 256 * 128, sc + OFF_H2, 256, 128, 1);
    k_fsm<<<64, 64>>>(sc + OFF_H2, W3 + (size_t)k * 128, fout);
}

extern "C" void kernel_launch(void* const* d_in, const int* in_sizes, int n_in,
                              void* d_out, int out_size) {
    const float* x   = (const float*)d_in[0];
    const int*   ei  = (const int*)d_in[1];
    const float* ew  = (const float*)d_in[2];
    const float* tgt = (const float*)d_in[3];
    const float* Wk  = (const float*)d_in[5];
    const float* W1  = (const float*)d_in[6];
    const float* W2  = (const float*)d_in[7];
    const float* W3  = (const float*)d_in[8];
    const float* lW  = (const float*)d_in[9];
    float* out = (float*)d_out;

    void* sp = nullptr;
    cudaGetSymbolAddress(&sp, g_scratch);
    float* sc = (float*)sp;
    int* perm = (int*)(sc + OFF_PERM);

    // zero Aw + cnt + deg (contiguous)
    int zc = (int)(OFF_DINV - OFF_AW);
    k_zero<<<(zc + 255) / 256, 256>>>(sc + OFF_AW, zc);

    // graph normalization
    int ne = NEDG + NTOT;
    k_deg<<<(ne + 255) / 256, 256>>>(ei, ew, sc + OFF_DEG);
    k_dinv<<<(NTOT + 255) / 256, 256>>>(sc + OFF_DEG, sc + OFF_DINV);
    k_adj<<<(ne + 255) / 256, 256>>>(ei, ew, sc + OFF_DINV, sc + OFF_AW, sc + OFF_CNT);

    // x_q = hop(hop(x))
    k_bgemmT<<<NBAT, 256>>>(sc + OFF_AW, x, sc + OFF_TMP);
    k_bgemmT<<<NBAT, 256>>>(sc + OFF_AW, sc + OFF_TMP, sc + OFF_XQ);

    // f1 = att(x, x_q), f2 = att(x, qt)
    run_attn(0, x, sc + OFF_XQ, 0, Wk, W1, W2, W3, sc, sc + OFF_F + 0 * NTOT);
    run_attn(1, x, tgt,         1, Wk, W1, W2, W3, sc, sc + OFF_F + 1 * NTOT);

    // edge softmax -> S, agg = S^T x
    k_sbuild<<<NBAT, 64>>>(sc + OFF_F + 0 * NTOT, sc + OFF_F + 1 * NTOT,
                           sc + OFF_CNT, sc + OFF_S);
    k_bgemmT<<<NBAT, 256>>>(sc + OFF_S, x, sc + OFF_AGG);

    // x_c
    k_gemm<<<dim3(64, 2), 256>>>(sc + OFF_AGG, lW,               sc + OFF_TMP,  128, 128, 0);
    k_gemm<<<dim3(64, 2), 256>>>(sc + OFF_AGG, lW + 128 * 128,   sc + OFF_TMP2, 128, 128, 0);
    k_xc<<<(NTOT * HDIM) / 256, 256>>>(x, sc + OFF_TMP, sc + OFF_TMP2, sc + OFF_XC);

    // x_q2 = hop(hop(x_c))
    k_bgemmT<<<NBAT, 256>>>(sc + OFF_AW, sc + OFF_XC, sc + OFF_TMP);
    k_bgemmT<<<NBAT, 256>>>(sc + OFF_AW, sc + OFF_TMP, sc + OFF_XQ);

    // g1 = att(x_c, x_q2), g2 = att(x_c, qt)
    run_attn(2, sc + OFF_XC, sc + OFF_XQ, 0, Wk, W1, W2, W3, sc, sc + OFF_F + 2 * NTOT);
    run_attn(3, sc + OFF_XC, tgt,         1, Wk, W1, W2, W3, sc, sc + OFF_F + 3 * NTOT);

    // cluster score + top-k
    k_score<<<NBAT, 64>>>(sc + OFF_F + 2 * NTOT, sc + OFF_F + 3 * NTOT, sc + OFF_SCORE);
    k_topk<<<NBAT, 64>>>(sc + OFF_SCORE, perm);

    // outputs
    k_zero<<<(NKEEP * NKEEP + 255) / 256, 256>>>(out + O_A2, NKEEP * NKEEP);
    k_a2<<<NBAT, 256>>>(sc + OFF_AW, sc + OFF_S, perm, out);
    k_xout<<<(NKEEP * HDIM + 255) / 256, 256>>>(x, sc + OFF_SCORE, perm, out);
}

// round 6
// speedup vs baseline: 1.0175x; 1.0175x over previous
#include <cuda_runtime.h>
#include <mma.h>
using namespace nvcuda;

// ---------------- problem constants ----------------
#define NTOT 4096      // B*n nodes
#define HDIM 128
#define NBAT 64
#define NEDG 131072    // given edges (self loops appended logically)
#define KSEL 52        // ceil(0.8*64)
#define NKEEP 3328     // 64*52

// output layout (float32 flat): x_out, A2, batch_out, perm
#define O_A2   425984LL
#define O_BAT  11501568LL
#define O_PERM 11504896LL

// scratch offsets (floats)
#define OFF_WM    0LL          // combined W1 weights: 4 x 384 x 256 = 393216
#define OFF_H0    524288LL     // h0 = [a, q, a*q]  4096 x 384
#define OFF_H1    2621440LL
#define OFF_H2    3670016LL
#define OFF_XQ    4194304LL
#define OFF_TMP   4718592LL
#define OFF_TMP2  5242880LL
#define OFF_AGG   5767168LL
#define OFF_XC    6291456LL
#define OFF_AW    6815744LL
#define OFF_CNT   7077888LL
#define OFF_DEG   7340032LL
#define OFF_DINV  7344128LL
#define OFF_S     7348224LL
#define OFF_F     7610368LL
#define OFF_SCORE 7626752LL
#define OFF_PERM  7630848LL
#define SCRATCH_TOTAL 7634176LL

__device__ float g_scratch[SCRATCH_TOTAL];

__device__ __forceinline__ float lrelu(float v) { return v >= 0.f ? v : 0.01f * v; }

typedef wmma::fragment<wmma::matrix_a, 16, 16, 8, wmma::precision::tf32, wmma::row_major> FragA;
typedef wmma::fragment<wmma::matrix_b, 16, 16, 8, wmma::precision::tf32, wmma::row_major> FragB;
typedef wmma::fragment<wmma::accumulator, 16, 16, 8, float> FragC;

// split raw fp32 fragment into tf32 hi + tf32 lo (3xTF32 scheme)
template <class F>
__device__ __forceinline__ void split_tf32(F& hi, F& lo) {
    #pragma unroll
    for (int t = 0; t < hi.num_elements; t++) {
        float r = hi.x[t];
        float h = wmma::__float_to_tf32(r);
        hi.x[t] = h;
        lo.x[t] = wmma::__float_to_tf32(r - h);
    }
}

__device__ __forceinline__ void mma3(FragC& d, const FragA& ah, const FragA& al,
                                     const FragB& bh, const FragB& bl) {
    wmma::mma_sync(d, al, bh, d);
    wmma::mma_sync(d, ah, bl, d);
    wmma::mma_sync(d, ah, bh, d);
}

// ---------------- generic zero ----------------
__global__ void k_zero(float* p, int n) {
    int i = blockIdx.x * 256 + threadIdx.x;
    if (i < n) p[i] = 0.f;
}

// ---------------- degree ----------------
__global__ void k_deg(const int* __restrict__ ei, const float* __restrict__ w,
                      float* __restrict__ deg) {
    int e = blockIdx.x * 256 + threadIdx.x;
    if (e < NEDG) atomicAdd(&deg[ei[NEDG + e]], w[e]);          // col-indexed
    else if (e < NEDG + NTOT) atomicAdd(&deg[e - NEDG], 1.0f);  // self loop
}

__global__ void k_dinv(const float* __restrict__ deg, float* __restrict__ dinv) {
    int i = blockIdx.x * 256 + threadIdx.x;
    if (i < NTOT) {
        float d = deg[i];
        dinv[i] = d > 0.f ? rsqrtf(fmaxf(d, 1e-12f)) : 0.f;
    }
}

// ---------------- dense per-batch adjacency (Aw = sum ew, cnt = multiplicity) --------
__global__ void k_adj(const int* __restrict__ ei, const float* __restrict__ w,
                      const float* __restrict__ dinv,
                      float* __restrict__ Aw, float* __restrict__ cnt) {
    int e = blockIdx.x * 256 + threadIdx.x;
    int r, c; float wv;
    if (e < NEDG)            { r = ei[e]; c = ei[NEDG + e]; wv = w[e]; }
    else if (e < NEDG + NTOT){ r = c = e - NEDG; wv = 1.f; }
    else return;
    float evw = dinv[r] * wv * dinv[c];
    size_t o = (size_t)(r >> 6) * 4096 + (size_t)(r & 63) * 64 + (c & 63);
    atomicAdd(&Aw[o], evw);
    atomicAdd(&cnt[o], 1.f);
}

// ---------------- combine W1 weights: Wm = [Wa+Wc; Wb-Wc; Wd]  (4 heads) ------------
__global__ void k_wmod(const float* __restrict__ W1, float* __restrict__ Wm) {
    int i = blockIdx.x * 256 + threadIdx.x;
    if (i >= 4 * 384 * 256) return;
    int c = i & 255;
    int r = (i >> 8) % 384;
    int h = i / (384 * 256);
    const float* Wh = W1 + (size_t)h * 512 * 256;
    float v;
    if (r < 128)      v = Wh[r * 256 + c] + Wh[(256 + r) * 256 + c];
    else if (r < 256) v = Wh[r * 256 + c] - Wh[(r + 128) * 256 + c];
    else              v = Wh[(r + 128) * 256 + c];
    Wm[i] = v;
}

// ---------------- per-batch out = M_b^T @ v_b  (64x64 @ 64x128), 3xTF32 -------------
__global__ void k_bgemmT(const float* __restrict__ M, const float* __restrict__ vin,
                         float* __restrict__ vout) {
    __shared__ float MsT[64][68];
    int b = blockIdx.x, tid = threadIdx.x;
    const float* Mb = M + (size_t)b * 4096;
    const float* vb = vin + (size_t)b * 8192;
    float* ob = vout + (size_t)b * 8192;
    for (int i = tid; i < 4096; i += 256) MsT[i & 63][i >> 6] = Mb[i];  // transpose
    __syncthreads();
    int warp = tid >> 5, wr = warp >> 2, wc = warp & 3;  // wr: 2 c-tiles of 32, wc: 4 h-tiles of 32
    FragC acc[2][2];
    #pragma unroll
    for (int i = 0; i < 2; i++)
        #pragma unroll
        for (int j = 0; j < 2; j++) wmma::fill_fragment(acc[i][j], 0.f);
    for (int k0 = 0; k0 < 64; k0 += 8) {
        FragA ah[2], al[2];
        #pragma unroll
        for (int i = 0; i < 2; i++) {
            wmma::load_matrix_sync(ah[i], &MsT[wr * 32 + i * 16][k0], 68);
            split_tf32(ah[i], al[i]);
        }
        #pragma unroll
        for (int j = 0; j < 2; j++) {
            FragB bh, bl;
            wmma::load_matrix_sync(bh, vb + (size_t)k0 * 128 + wc * 32 + j * 16, 128);
            split_tf32(bh, bl);
            #pragma unroll
            for (int i = 0; i < 2; i++) mma3(acc[i][j], ah[i], al[i], bh, bl);
        }
    }
    #pragma unroll
    for (int i = 0; i < 2; i++)
        #pragma unroll
        for (int j = 0; j < 2; j++)
            wmma::store_matrix_sync(ob + (size_t)(wr * 32 + i * 16) * 128 + wc * 32 + j * 16,
                                    acc[i][j], 128, wmma::mem_row_major);
}

// ---------------- 3xTF32 GEMM: C[N x MO] = A[N x K] @ W[K x MO], fused epilogues ----
// mode 0: plain   1: leaky   2: h0 epilogue (dense q)   3: h0 epilogue (target q)
// mode 4: dual-weight (W, Wb) + x_c combine epilogue (q = x, MO = 128)
#define BK 32
__global__ void k_gemm(const float* __restrict__ A, const float* __restrict__ W,
                       float* __restrict__ C, int K, int MO, int mode,
                       const float* __restrict__ q, const float* __restrict__ Wb) {
    __shared__ float As[64][BK + 4];
    __shared__ float Ws[BK][68];
    __shared__ float Ws2[BK][68];
    __shared__ float Cs[64][68];
    int tid = threadIdx.x;
    int m0 = blockIdx.x * 64, n0 = blockIdx.y * 64;
    int warp = tid >> 5, wr = warp >> 1, wc = warp & 1;  // 4 row-tiles x 2 col-halves
    FragC acc[2], acc2[2];
    #pragma unroll
    for (int t = 0; t < 2; t++) wmma::fill_fragment(acc[t], 0.f);
    if (mode == 4) {
        #pragma unroll
        for (int t = 0; t < 2; t++) wmma::fill_fragment(acc2[t], 0.f);
    }

    for (int k0 = 0; k0 < K; k0 += BK) {
        #pragma unroll
        for (int s = 0; s < 2; s++) {
            int i = tid + s * 256;
            *(float4*)&As[i >> 3][(i & 7) * 4] =
                *(const float4*)(A + (size_t)(m0 + (i >> 3)) * K + k0 + (i & 7) * 4);
            *(float4*)&Ws[i >> 4][(i & 15) * 4] =
                *(const float4*)(W + (size_t)(k0 + (i >> 4)) * MO + n0 + (i & 15) * 4);
        }
        if (mode == 4) {
            #pragma unroll
            for (int s = 0; s < 2; s++) {
                int i = tid + s * 256;
                *(float4*)&Ws2[i >> 4][(i & 15) * 4] =
                    *(const float4*)(Wb + (size_t)(k0 + (i >> 4)) * MO + n0 + (i & 15) * 4);
            }
        }
        __syncthreads();
        #pragma unroll
        for (int kk = 0; kk < BK; kk += 8) {
            FragA ah, al;
            wmma::load_matrix_sync(ah, &As[wr * 16][kk], BK + 4);
            split_tf32(ah, al);
            #pragma unroll
            for (int t = 0; t < 2; t++) {
                FragB bh, bl;
                wmma::load_matrix_sync(bh, &Ws[kk][wc * 32 + t * 16], 68);
                split_tf32(bh, bl);
                mma3(acc[t], ah, al, bh, bl);
                if (mode == 4) {
                    FragB ch, cl;
                    wmma::load_matrix_sync(ch, &Ws2[kk][wc * 32 + t * 16], 68);
                    split_tf32(ch, cl);
                    mma3(acc2[t], ah, al, ch, cl);
                }
            }
        }
        __syncthreads();
    }

    if (mode <= 1) {
        #pragma unroll
        for (int t = 0; t < 2; t++) {
            if (mode == 1) {
                #pragma unroll
                for (int e = 0; e < acc[t].num_elements; e++) acc[t].x[e] = lrelu(acc[t].x[e]);
            }
            wmma::store_matrix_sync(C + (size_t)(m0 + wr * 16) * MO + n0 + wc * 32 + t * 16,
                                    acc[t], MO, wmma::mem_row_major);
        }
        return;
    }

    // stage tile to shared for element-addressed epilogues
    #pragma unroll
    for (int t = 0; t < 2; t++)
        wmma::store_matrix_sync(&Cs[wr * 16][wc * 32 + t * 16], acc[t], 68, wmma::mem_row_major);
    __syncthreads();

    int r = tid >> 2, cbase = (tid & 3) * 16;
    int node = m0 + r;
    if (mode == 2 || mode == 3) {
        float* h = C + (size_t)node * 384;  // C = h0 base, layout [a | q | a*q]
        const float* qrow = (mode == 2) ? q + (size_t)node * 128
                                        : q + (size_t)(node >> 6) * 128;
        #pragma unroll 4
        for (int j = 0; j < 16; j++) {
            int kg = n0 + cbase + j;
            float av = Cs[r][cbase + j];
            float qv = qrow[kg];
            h[kg] = av; h[128 + kg] = qv; h[256 + kg] = av * qv;
        }
    } else {  // mode 4: x_c = 0.5*(lrelu(x+t0)+lrelu(x+t1))
        float t0v[16];
        #pragma unroll
        for (int j = 0; j < 16; j++) t0v[j] = Cs[r][cbase + j];
        __syncthreads();
        #pragma unroll
        for (int t = 0; t < 2; t++)
            wmma::store_matrix_sync(&Cs[wr * 16][wc * 32 + t * 16], acc2[t], 68, wmma::mem_row_major);
        __syncthreads();
        const float* xrow = q + (size_t)node * 128;
        #pragma unroll 4
        for (int j = 0; j < 16; j++) {
            int kg = n0 + cbase + j;
            float xv = xrow[kg];
            C[(size_t)node * 128 + kg] = 0.5f * (lrelu(xv + t0v[j]) + lrelu(xv + Cs[r][cbase + j]));
        }
    }
}

// ---------------- fused W3 dot + leaky + per-batch softmax ----------------
__global__ void k_fsm(const float* __restrict__ h2, const float* __restrict__ W3,
                      float* __restrict__ fout) {
    int b = blockIdx.x, t = threadIdx.x;   // 64 threads
    __shared__ float w3[128];
    __shared__ float red[64];
    w3[t] = W3[t]; w3[64 + t] = W3[64 + t];
    __syncthreads();
    int row = b * 64 + t;
    const float* h = h2 + (size_t)row * 128;
    float dot = 0.f;
    #pragma unroll 8
    for (int k = 0; k < 128; k++) dot += h[k] * w3[k];
    float v = lrelu(dot);
    red[t] = v; __syncthreads();
    for (int off = 32; off > 0; off >>= 1) {
        if (t < off) red[t] = fmaxf(red[t], red[t + off]);
        __syncthreads();
    }
    float m = red[0]; __syncthreads();
    float e = expf(v - m);
    red[t] = e; __syncthreads();
    for (int off = 32; off > 0; off >>= 1) {
        if (t < off) red[t] += red[t + off];
        __syncthreads();
    }
    fout[row] = e / red[0];
}

// ---------------- cluster score: softmax(g1+g2) per batch ----------------
__global__ void k_score(const float* __restrict__ g1, const float* __restrict__ g2,
                        float* __restrict__ score) {
    int b = blockIdx.x, t = threadIdx.x;
    __shared__ float red[64];
    int row = b * 64 + t;
    float v = g1[row] + g2[row];
    red[t] = v; __syncthreads();
    for (int off = 32; off > 0; off >>= 1) {
        if (t < off) red[t] = fmaxf(red[t], red[t + off]);
        __syncthreads();
    }
    float m = red[0]; __syncthreads();
    float e = expf(v - m);
    red[t] = e; __syncthreads();
    for (int off = 32; off > 0; off >>= 1) {
        if (t < off) red[t] += red[t + off];
        __syncthreads();
    }
    score[row] = e / red[0];
}

// ---------------- edge softmax -> dense S block  (thread = target column c) ---------
__global__ void k_sbuild(const float* __restrict__ f1, const float* __restrict__ f2,
                         const float* __restrict__ cnt, float* __restrict__ Sm) {
    int b = blockIdx.x, c = threadIdx.x;
    __shared__ float f2s[64];
    f2s[c] = f2[b * 64 + c];
    __syncthreads();
    float f1c = f1[b * 64 + c];
    const float* Cb = cnt + (size_t)b * 4096;
    float* Sb = Sm + (size_t)b * 4096;
    float m = -1e30f;
    for (int r = 0; r < 64; r++) m = fmaxf(m, lrelu(f1c + f2s[r]));  // shift-invariant
    float d = 0.f;
    for (int r = 0; r < 64; r++) {
        float val = lrelu(f1c + f2s[r]);
        float e = Cb[r * 64 + c] * expf(val - m);   // duplicates via cnt; cnt=0 -> 0
        Sb[r * 64 + c] = e; d += e;
    }
    float inv = 1.f / d;                            // self-loop guarantees d > 0
    for (int r = 0; r < 64; r++) Sb[r * 64 + c] *= inv;
}

// ---------------- per-batch top-52 (descending, stable ties) ----------------
__global__ void k_topk(const float* __restrict__ score, int* __restrict__ perm) {
    int b = blockIdx.x, t = threadIdx.x;   // 64 threads
    __shared__ float s[64];
    __shared__ float rv[64];
    __shared__ int   ri[64];
    s[t] = score[b * 64 + t];
    __syncthreads();
    for (int j = 0; j < KSEL; j++) {
        rv[t] = s[t]; ri[t] = t; __syncthreads();
        for (int off = 32; off > 0; off >>= 1) {
            if (t < off) {
                float ov = rv[t + off]; int oi = ri[t + off];
                if (ov > rv[t] || (ov == rv[t] && oi < ri[t])) { rv[t] = ov; ri[t] = oi; }
            }
            __syncthreads();
        }
        if (t == 0) { perm[b * KSEL + j] = ri[0]; s[ri[0]] = -3.4e38f; }
        __syncthreads();
    }
}

// ---------------- outputs: x_out, batch_out, perm ----------------
__global__ void k_xout(const float* __restrict__ x, const float* __restrict__ score,
                       const int* __restrict__ perm, float* __restrict__ out) {
    int t = blockIdx.x * 256 + threadIdx.x;
    if (t >= NKEEP * HDIM) return;
    int j = t >> 7, k = t & 127;
    int b = j / KSEL;
    int pg = b * 64 + perm[j];
    out[t] = x[(size_t)pg * 128 + k] * score[pg];
    if (k == 0) {
        out[O_BAT + j]  = (float)b;
        out[O_PERM + j] = (float)pg;
    }
}

// ---------------- A2 diagonal block: Sp^T (Aw Sp), diag = 1 ----------------
__global__ void k_a2(const float* __restrict__ Aw, const float* __restrict__ Sm,
                     const int* __restrict__ perm, float* __restrict__ out) {
    int b = blockIdx.x, tid = threadIdx.x;   // 256 threads
    __shared__ float Aws[64][65];
    __shared__ float Sp[64][53];
    __shared__ float Ms[64][53];
    __shared__ int idx[52];
    const float* Ab = Aw + (size_t)b * 4096;
    for (int i = tid; i < 4096; i += 256) Aws[i >> 6][i & 63] = Ab[i];
    if (tid < 52) idx[tid] = perm[b * KSEL + tid];
    __syncthreads();
    const float* Sb = Sm + (size_t)b * 4096;
    for (int i = tid; i < 64 * 52; i += 256) {
        int r = i / 52, j = i % 52;
        Sp[r][j] = Sb[r * 64 + idx[j]];
    }
    __syncthreads();
    for (int i = tid; i < 64 * 52; i += 256) {
        int r = i / 52, j = i % 52;
        float acc = 0.f;
        #pragma unroll 8
        for (int c = 0; c < 64; c++) acc += Aws[r][c] * Sp[c][j];
        Ms[r][j] = acc;
    }
    __syncthreads();
    for (int i = tid; i < 52 * 52; i += 256) {
        int ii = i / 52, j = i % 52;
        float v;
        if (ii == j) v = 1.f;
        else {
            v = 0.f;
            #pragma unroll 8
            for (int r = 0; r < 64; r++) v += Sp[r][ii] * Ms[r][j];
        }
        long long gi = (long long)b * KSEL + ii;
        out[O_A2 + gi * NKEEP + b * KSEL + j] = v;
    }
}

// ---------------- host side ----------------
static void run_attn(int k, const float* kv, const float* q, int qtar,
                     const float* Wk, const float* Wm, const float* W2, const float* W3,
                     float* sc, float* fout) {
    // Wk GEMM with fused h0 build: h0 = [a, q, a*q], a = kv @ Wk
    k_gemm<<<dim3(64, 2), 256>>>(kv, Wk + (size_t)k * 128 * 128, sc + OFF_H0,
                                 128, 128, qtar ? 3 : 2, q, nullptr);
    // h1 = leaky(h0 @ Wm)   (K reduced 512 -> 384 via weight precombination)
    k_gemm<<<dim3(64, 4), 256>>>(sc + OFF_H0, Wm + (size_t)k * 384 * 256, sc + OFF_H1,
                                 384, 256, 1, nullptr, nullptr);
    // h2 = leaky(h1 @ W2)
    k_gemm<<<dim3(64, 2), 256>>>(sc + OFF_H1, W2 + (size_t)k * 256 * 128, sc + OFF_H2,
                                 256, 128, 1, nullptr, nullptr);
    k_fsm<<<64, 64>>>(sc + OFF_H2, W3 + (size_t)k * 128, fout);
}

extern "C" void kernel_launch(void* const* d_in, const int* in_sizes, int n_in,
                              void* d_out, int out_size) {
    const float* x   = (const float*)d_in[0];
    const int*   ei  = (const int*)d_in[1];
    const float* ew  = (const float*)d_in[2];
    const float* tgt = (const float*)d_in[3];
    const float* Wk  = (const float*)d_in[5];
    const float* W1  = (const float*)d_in[6];
    const float* W2  = (const float*)d_in[7];
    const float* W3  = (const float*)d_in[8];
    const float* lW  = (const float*)d_in[9];
    float* out = (float*)d_out;

    void* sp = nullptr;
    cudaGetSymbolAddress(&sp, g_scratch);
    float* sc = (float*)sp;
    int* perm = (int*)(sc + OFF_PERM);

    // combined W1 weights (once, weights are constant per launch)
    k_wmod<<<(4 * 384 * 256) / 256, 256>>>(W1, sc + OFF_WM);

    // zero Aw + cnt + deg (contiguous)
    int zc = (int)(OFF_DINV - OFF_AW);
    k_zero<<<(zc + 255) / 256, 256>>>(sc + OFF_AW, zc);

    // graph normalization
    int ne = NEDG + NTOT;
    k_deg<<<(ne + 255) / 256, 256>>>(ei, ew, sc + OFF_DEG);
    k_dinv<<<(NTOT + 255) / 256, 256>>>(sc + OFF_DEG, sc + OFF_DINV);
    k_adj<<<(ne + 255) / 256, 256>>>(ei, ew, sc + OFF_DINV, sc + OFF_AW, sc + OFF_CNT);

    // x_q = hop(hop(x))
    k_bgemmT<<<NBAT, 256>>>(sc + OFF_AW, x, sc + OFF_TMP);
    k_bgemmT<<<NBAT, 256>>>(sc + OFF_AW, sc + OFF_TMP, sc + OFF_XQ);

    // f1 = att(x, x_q), f2 = att(x, qt)
    run_attn(0, x, sc + OFF_XQ, 0, Wk, sc + OFF_WM, W2, W3, sc, sc + OFF_F + 0 * NTOT);
    run_attn(1, x, tgt,         1, Wk, sc + OFF_WM, W2, W3, sc, sc + OFF_F + 1 * NTOT);

    // edge softmax -> S, agg = S^T x
    k_sbuild<<<NBAT, 64>>>(sc + OFF_F + 0 * NTOT, sc + OFF_F + 1 * NTOT,
                           sc + OFF_CNT, sc + OFF_S);
    k_bgemmT<<<NBAT, 256>>>(sc + OFF_S, x, sc + OFF_AGG);

    // x_c = 0.5*(lrelu(x + agg@W0) + lrelu(x + agg@W1))  (fused dual-weight GEMM)
    k_gemm<<<dim3(64, 2), 256>>>(sc + OFF_AGG, lW, sc + OFF_XC, 128, 128, 4,
                                 x, lW + 128 * 128);

    // x_q2 = hop(hop(x_c))
    k_bgemmT<<<NBAT, 256>>>(sc + OFF_AW, sc + OFF_XC, sc + OFF_TMP);
    k_bgemmT<<<NBAT, 256>>>(sc + OFF_AW, sc + OFF_TMP, sc + OFF_XQ);

    // g1 = att(x_c, x_q2), g2 = att(x_c, qt)
    run_attn(2, sc + OFF_XC, sc + OFF_XQ, 0, Wk, sc + OFF_WM, W2, W3, sc, sc + OFF_F + 2 * NTOT);
    run_attn(3, sc + OFF_XC, tgt,         1, Wk, sc + OFF_WM, W2, W3, sc, sc + OFF_F + 3 * NTOT);

    // cluster score + top-k
    k_score<<<NBAT, 64>>>(sc + OFF_F + 2 * NTOT, sc + OFF_F + 3 * NTOT, sc + OFF_SCORE);
    k_topk<<<NBAT, 64>>>(sc + OFF_SCORE, perm);

    // outputs
    k_zero<<<(NKEEP * NKEEP + 255) / 256, 256>>>(out + O_A2, NKEEP * NKEEP);
    k_a2<<<NBAT, 256>>>(sc + OFF_AW, sc + OFF_S, perm, out);
    k_xout<<<(NKEEP * HDIM + 255) / 256, 256>>>(x, sc + OFF_SCORE, perm, out);
}

// round 7
// speedup vs baseline: 1.0393x; 1.0214x over previous
#include <cuda_runtime.h>
#include <mma.h>
using namespace nvcuda;

// ---------------- problem constants ----------------
#define NTOT 4096
#define HDIM 128
#define NBAT 64
#define NEDG 131072
#define KSEL 52
#define NKEEP 3328
#define NBLK 128
#define NTHR 256

// output layout (float32 flat): x_out, A2, batch_out, perm
#define O_A2   425984LL
#define O_BAT  11501568LL
#define O_PERM 11504896LL

// scratch offsets (floats)
#define OFF_WM    0LL          // combined W1: 4 x 384 x 256
#define OFF_H0    393216LL     // 2 x (4096 x 384)
#define OFF_H1    3538944LL    // 2 x (4096 x 256)
#define OFF_H2    5636096LL    // 2 x (4096 x 128)
#define OFF_XQ    6684672LL
#define OFF_TMP   7208960LL
#define OFF_AGG   7733248LL
#define OFF_XC    8257536LL
#define OFF_AW    8781824LL
#define OFF_CNT   9043968LL
#define OFF_DEG   9306112LL
#define OFF_S     9310208LL
#define OFF_SCORE 9572352LL
#define OFF_PERM  9576448LL
#define SCRATCH_TOTAL 9579776LL

__device__ float g_scratch[SCRATCH_TOTAL];
__device__ unsigned g_bar[16 * 32];   // one padded ticket counter per barrier

__device__ __forceinline__ float lrelu(float v) { return v >= 0.f ? v : 0.01f * v; }

// monotonic-ticket grid barrier; gpu-scope fences flush L1D (CCTL.IVALL)
__device__ __forceinline__ void gsync(int i) {
    __syncthreads();
    if (threadIdx.x == 0) {
        __threadfence();
        unsigned t = atomicAdd(&g_bar[i * 32], 1u);
        unsigned target = (t / NBLK + 1u) * NBLK;
        while ((int)(*(volatile unsigned*)&g_bar[i * 32] - target) < 0) { }
        __threadfence();
    }
    __syncthreads();
}

typedef wmma::fragment<wmma::matrix_a, 16, 16, 8, wmma::precision::tf32, wmma::row_major> FragA;
typedef wmma::fragment<wmma::matrix_b, 16, 16, 8, wmma::precision::tf32, wmma::row_major> FragB;
typedef wmma::fragment<wmma::accumulator, 16, 16, 8, float> FragC;

template <class F>
__device__ __forceinline__ void split_tf32(F& hi, F& lo) {
    #pragma unroll
    for (int t = 0; t < hi.num_elements; t++) {
        float r = hi.x[t];
        float h = wmma::__float_to_tf32(r);
        hi.x[t] = h;
        lo.x[t] = wmma::__float_to_tf32(r - h);
    }
}

__device__ __forceinline__ void mma3(FragC& d, const FragA& ah, const FragA& al,
                                     const FragB& bh, const FragB& bl) {
    wmma::mma_sync(d, al, bh, d);
    wmma::mma_sync(d, ah, bl, d);
    wmma::mma_sync(d, ah, bh, d);
}

// ---------------- 3xTF32 GEMM tile (64x64), fused epilogues ----------------
// mode 0: plain  1: leaky  2: h0 epi (dense q)  3: h0 epi (target q)  4: dual-W + x_c
#define BK 32
__device__ void dev_gemm(const float* __restrict__ A, const float* __restrict__ W,
                         float* __restrict__ C, int K, int MO, int mode,
                         const float* __restrict__ q, const float* __restrict__ Wb,
                         int m0, int n0, float* sm) {
    float* As  = sm;          // [64][36]
    float* Ws  = sm + 2304;   // [32][68]
    float* Ws2 = sm + 4480;   // [32][68]
    float* Cs  = sm + 6656;   // [64][68]
    int tid = threadIdx.x;
    int warp = tid >> 5, wr = warp >> 1, wc = warp & 1;
    FragC acc[2], acc2[2];
    #pragma unroll
    for (int t = 0; t < 2; t++) wmma::fill_fragment(acc[t], 0.f);
    if (mode == 4) {
        #pragma unroll
        for (int t = 0; t < 2; t++) wmma::fill_fragment(acc2[t], 0.f);
    }

    for (int k0 = 0; k0 < K; k0 += BK) {
        #pragma unroll
        for (int s = 0; s < 2; s++) {
            int i = tid + s * 256;
            *(float4*)&As[(i >> 3) * 36 + (i & 7) * 4] =
                *(const float4*)(A + (size_t)(m0 + (i >> 3)) * K + k0 + (i & 7) * 4);
            *(float4*)&Ws[(i >> 4) * 68 + (i & 15) * 4] =
                *(const float4*)(W + (size_t)(k0 + (i >> 4)) * MO + n0 + (i & 15) * 4);
        }
        if (mode == 4) {
            #pragma unroll
            for (int s = 0; s < 2; s++) {
                int i = tid + s * 256;
                *(float4*)&Ws2[(i >> 4) * 68 + (i & 15) * 4] =
                    *(const float4*)(Wb + (size_t)(k0 + (i >> 4)) * MO + n0 + (i & 15) * 4);
            }
        }
        __syncthreads();
        #pragma unroll
        for (int kk = 0; kk < BK; kk += 8) {
            FragA ah, al;
            wmma::load_matrix_sync(ah, &As[(wr * 16) * 36 + kk], 36);
            split_tf32(ah, al);
            #pragma unroll
            for (int t = 0; t < 2; t++) {
                FragB bh, bl;
                wmma::load_matrix_sync(bh, &Ws[kk * 68 + wc * 32 + t * 16], 68);
                split_tf32(bh, bl);
                mma3(acc[t], ah, al, bh, bl);
                if (mode == 4) {
                    FragB ch, cl;
                    wmma::load_matrix_sync(ch, &Ws2[kk * 68 + wc * 32 + t * 16], 68);
                    split_tf32(ch, cl);
                    mma3(acc2[t], ah, al, ch, cl);
                }
            }
        }
        __syncthreads();
    }

    if (mode <= 1) {
        #pragma unroll
        for (int t = 0; t < 2; t++) {
            if (mode == 1) {
                #pragma unroll
                for (int e = 0; e < acc[t].num_elements; e++) acc[t].x[e] = lrelu(acc[t].x[e]);
            }
            wmma::store_matrix_sync(C + (size_t)(m0 + wr * 16) * MO + n0 + wc * 32 + t * 16,
                                    acc[t], MO, wmma::mem_row_major);
        }
        return;
    }

    #pragma unroll
    for (int t = 0; t < 2; t++)
        wmma::store_matrix_sync(&Cs[(wr * 16) * 68 + wc * 32 + t * 16], acc[t], 68,
                                wmma::mem_row_major);
    __syncthreads();

    int r = tid >> 2, cbase = (tid & 3) * 16;
    int node = m0 + r;
    if (mode == 2 || mode == 3) {
        float* h = C + (size_t)node * 384;  // [a | q | a*q]
        const float* qrow = (mode == 2) ? q + (size_t)node * 128
                                        : q + (size_t)(node >> 6) * 128;
        #pragma unroll 4
        for (int j = 0; j < 16; j++) {
            int kg = n0 + cbase + j;
            float av = Cs[r * 68 + cbase + j];
            float qv = qrow[kg];
            h[kg] = av; h[128 + kg] = qv; h[256 + kg] = av * qv;
        }
    } else {  // mode 4
        float t0v[16];
        #pragma unroll
        for (int j = 0; j < 16; j++) t0v[j] = Cs[r * 68 + cbase + j];
        __syncthreads();
        #pragma unroll
        for (int t = 0; t < 2; t++)
            wmma::store_matrix_sync(&Cs[(wr * 16) * 68 + wc * 32 + t * 16], acc2[t], 68,
                                    wmma::mem_row_major);
        __syncthreads();
        const float* xrow = q + (size_t)node * 128;
        #pragma unroll 4
        for (int j = 0; j < 16; j++) {
            int kg = n0 + cbase + j;
            float xv = xrow[kg];
            C[(size_t)node * 128 + kg] =
                0.5f * (lrelu(xv + t0v[j]) + lrelu(xv + Cs[r * 68 + cbase + j]));
        }
    }
    __syncthreads();
}

// ---------------- per-batch out = M^T @ v (64x64 @ 64x128), 3xTF32 ----------------
__device__ void dev_bgemmT(const float* __restrict__ Mb, const float* __restrict__ vb,
                           float* __restrict__ ob, float* sm) {
    float* MsT = sm;  // [64][68]
    int tid = threadIdx.x;
    for (int i = tid; i < 4096; i += NTHR) MsT[(i & 63) * 68 + (i >> 6)] = Mb[i];
    __syncthreads();
    int warp = tid >> 5, wr = warp >> 2, wc = warp & 3;
    FragC acc[2][2];
    #pragma unroll
    for (int i = 0; i < 2; i++)
        #pragma unroll
        for (int j = 0; j < 2; j++) wmma::fill_fragment(acc[i][j], 0.f);
    for (int k0 = 0; k0 < 64; k0 += 8) {
        FragA ah[2], al[2];
        #pragma unroll
        for (int i = 0; i < 2; i++) {
            wmma::load_matrix_sync(ah[i], &MsT[(wr * 32 + i * 16) * 68 + k0], 68);
            split_tf32(ah[i], al[i]);
        }
        #pragma unroll
        for (int j = 0; j < 2; j++) {
            FragB bh, bl;
            wmma::load_matrix_sync(bh, vb + (size_t)k0 * 128 + wc * 32 + j * 16, 128);
            split_tf32(bh, bl);
            #pragma unroll
            for (int i = 0; i < 2; i++) mma3(acc[i][j], ah[i], al[i], bh, bl);
        }
    }
    #pragma unroll
    for (int i = 0; i < 2; i++)
        #pragma unroll
        for (int j = 0; j < 2; j++)
            wmma::store_matrix_sync(ob + (size_t)(wr * 32 + i * 16) * 128 + wc * 32 + j * 16,
                                    acc[i][j], 128, wmma::mem_row_major);
    __syncthreads();
}

// ---------------- W3 dot + leaky + per-batch softmax (64 rows) ----------------
__device__ float fsm_dev(const float* __restrict__ h2b, const float* __restrict__ W3h,
                         float* red) {
    int t = threadIdx.x;
    float v = 0.f;
    if (t < 64) {
        const float* h = h2b + (size_t)t * 128;
        float dot = 0.f;
        #pragma unroll 8
        for (int k = 0; k < 128; k++) dot += h[k] * W3h[k];
        v = lrelu(dot);
        red[t] = v;
    }
    __syncthreads();
    for (int off = 32; off > 0; off >>= 1) {
        if (t < off) red[t] = fmaxf(red[t], red[t + off]);
        __syncthreads();
    }
    float m = red[0];
    __syncthreads();
    float e = 0.f;
    if (t < 64) { e = expf(v - m); red[t] = e; }
    __syncthreads();
    for (int off = 32; off > 0; off >>= 1) {
        if (t < off) red[t] += red[t + off];
        __syncthreads();
    }
    float r = (t < 64) ? e / red[0] : 0.f;
    __syncthreads();
    return r;
}

// ---------------- attention pair (2 heads), 3 GEMM phases + 3 barriers ----------------
__device__ void attn_pair(const float* __restrict__ kv, const float* __restrict__ qdense,
                          const float* __restrict__ tgt, int khead,
                          const float* __restrict__ Wk, const float* __restrict__ W2,
                          float* sc, float* sm, int bar0) {
    int bid = blockIdx.x;
    for (int tix = bid; tix < 256; tix += NBLK) {       // gemm1 + h0 build
        int head = tix >> 7, rem = tix & 127;
        int m0 = (rem & 63) * 64, n0 = (rem >> 6) * 64;
        dev_gemm(kv, Wk + (size_t)(khead + head) * 16384,
                 sc + OFF_H0 + (size_t)head * 1572864, 128, 128,
                 head ? 3 : 2, head ? tgt : qdense, nullptr, m0, n0, sm);
    }
    gsync(bar0);
    for (int tix = bid; tix < 512; tix += NBLK) {       // h1 = leaky(h0 @ Wm)
        int head = tix >> 8, rem = tix & 255;
        int m0 = (rem & 63) * 64, n0 = (rem >> 6) * 64;
        dev_gemm(sc + OFF_H0 + (size_t)head * 1572864,
                 sc + OFF_WM + (size_t)(khead + head) * 98304,
                 sc + OFF_H1 + (size_t)head * 1048576, 384, 256, 1,
                 nullptr, nullptr, m0, n0, sm);
    }
    gsync(bar0 + 1);
    for (int tix = bid; tix < 256; tix += NBLK) {       // h2 = leaky(h1 @ W2)
        int head = tix >> 7, rem = tix & 127;
        int m0 = (rem & 63) * 64, n0 = (rem >> 6) * 64;
        dev_gemm(sc + OFF_H1 + (size_t)head * 1048576,
                 W2 + (size_t)(khead + head) * 32768,
                 sc + OFF_H2 + (size_t)head * 524288, 256, 128, 1,
                 nullptr, nullptr, m0, n0, sm);
    }
    gsync(bar0 + 2);
}

// ==================== megakernel ====================
__global__ void __launch_bounds__(NTHR, 1)
mega(const float* __restrict__ x, const int* __restrict__ ei,
     const float* __restrict__ ew, const float* __restrict__ tgt,
     const float* __restrict__ Wk, const float* __restrict__ W1,
     const float* __restrict__ W2, const float* __restrict__ W3,
     const float* __restrict__ lW, float* __restrict__ out) {
    __shared__ __align__(16) float sm[12288];   // 48 KB
    float* sc = g_scratch;
    int bid = blockIdx.x, tid = threadIdx.x;
    int gth = bid * NTHR + tid;
    const int GSTR = NBLK * NTHR;

    // ---- B0: combined W1 weights, zero scratch (Aw,cnt,deg), zero A2 ----
    for (int i = gth; i < 4 * 384 * 256; i += GSTR) {
        int c = i & 255, r = (i >> 8) % 384, h = i / (384 * 256);
        const float* Wh = W1 + (size_t)h * 512 * 256;
        float v;
        if (r < 128)      v = Wh[r * 256 + c] + Wh[(256 + r) * 256 + c];
        else if (r < 256) v = Wh[r * 256 + c] - Wh[(r + 128) * 256 + c];
        else              v = Wh[(r + 128) * 256 + c];
        sc[OFF_WM + i] = v;
    }
    {
        float4 z = make_float4(0.f, 0.f, 0.f, 0.f);
        float4* p = (float4*)(sc + OFF_AW);
        for (int i = gth; i < 528384 / 4; i += GSTR) p[i] = z;
        float4* p2 = (float4*)(out + O_A2);
        for (int i = gth; i < (NKEEP * NKEEP) / 4; i += GSTR) p2[i] = z;
    }
    gsync(0);

    // ---- B1: degree ----
    for (int e = gth; e < NEDG + NTOT; e += GSTR) {
        if (e < NEDG) atomicAdd(&sc[OFF_DEG + ei[NEDG + e]], ew[e]);
        else          atomicAdd(&sc[OFF_DEG + e - NEDG], 1.0f);
    }
    gsync(1);

    // ---- B2: dense adjacency with inline dinv ----
    for (int e = gth; e < NEDG + NTOT; e += GSTR) {
        int r, c; float wv;
        if (e < NEDG) { r = ei[e]; c = ei[NEDG + e]; wv = ew[e]; }
        else          { r = c = e - NEDG; wv = 1.f; }
        float dr = sc[OFF_DEG + r], dc = sc[OFF_DEG + c];
        float ir = dr > 0.f ? rsqrtf(fmaxf(dr, 1e-12f)) : 0.f;
        float ic = dc > 0.f ? rsqrtf(fmaxf(dc, 1e-12f)) : 0.f;
        float evw = ir * wv * ic;
        int o = ((r >> 6) << 12) + ((r & 63) << 6) + (c & 63);
        atomicAdd(&sc[OFF_AW + o], evw);
        atomicAdd(&sc[OFF_CNT + o], 1.f);
    }
    gsync(2);

    // ---- B3/B4: x_q = hop(hop(x)) ----
    if (bid < NBAT)
        dev_bgemmT(sc + OFF_AW + (size_t)bid * 4096, x + (size_t)bid * 8192,
                   sc + OFF_TMP + (size_t)bid * 8192, sm);
    gsync(3);
    if (bid < NBAT)
        dev_bgemmT(sc + OFF_AW + (size_t)bid * 4096, sc + OFF_TMP + (size_t)bid * 8192,
                   sc + OFF_XQ + (size_t)bid * 8192, sm);
    gsync(4);

    // ---- B5-B7: f1 = att(x, x_q), f2 = att(x, qt) ----
    attn_pair(x, sc + OFF_XQ, tgt, 0, Wk, W2, sc, sm, 5);

    // ---- B8: per-batch fsm(f1), fsm(f2), edge-softmax S, agg = S^T x ----
    if (bid < NBAT) {
        float* red = sm;
        float* f1s = sm + 64;
        float* f2s = sm + 128;
        float f1v = fsm_dev(sc + OFF_H2 + (size_t)bid * 8192, W3, red);
        float f2v = fsm_dev(sc + OFF_H2 + 524288 + (size_t)bid * 8192, W3 + 128, red);
        if (tid < 64) { f1s[tid] = f1v; f2s[tid] = f2v; }
        __syncthreads();
        if (tid < 64) {
            int c = tid;
            float f1c = f1s[c];
            const float* Cb = sc + OFF_CNT + (size_t)bid * 4096;
            float* Sb = sc + OFF_S + (size_t)bid * 4096;
            float m = -1e30f;
            for (int r = 0; r < 64; r++) m = fmaxf(m, lrelu(f1c + f2s[r]));
            float d = 0.f;
            for (int r = 0; r < 64; r++) {
                float val = lrelu(f1c + f2s[r]);
                float e = Cb[r * 64 + c] * expf(val - m);
                Sb[r * 64 + c] = e; d += e;
            }
            float inv = 1.f / d;
            for (int r = 0; r < 64; r++) Sb[r * 64 + c] *= inv;
        }
        __syncthreads();
        dev_bgemmT(sc + OFF_S + (size_t)bid * 4096, x + (size_t)bid * 8192,
                   sc + OFF_AGG + (size_t)bid * 8192, sm + 256);
    }
    gsync(8);

    // ---- B9: x_c = 0.5*(lrelu(x+agg@W0)+lrelu(x+agg@W1)) ----
    for (int tix = bid; tix < 128; tix += NBLK) {
        int m0 = (tix & 63) * 64, n0 = (tix >> 6) * 64;
        dev_gemm(sc + OFF_AGG, lW, sc + OFF_XC, 128, 128, 4, x, lW + 16384, m0, n0, sm);
    }
    gsync(9);

    // ---- B10/B11: x_q2 = hop(hop(x_c)) ----
    if (bid < NBAT)
        dev_bgemmT(sc + OFF_AW + (size_t)bid * 4096, sc + OFF_XC + (size_t)bid * 8192,
                   sc + OFF_TMP + (size_t)bid * 8192, sm);
    gsync(10);
    if (bid < NBAT)
        dev_bgemmT(sc + OFF_AW + (size_t)bid * 4096, sc + OFF_TMP + (size_t)bid * 8192,
                   sc + OFF_XQ + (size_t)bid * 8192, sm);
    gsync(11);

    // ---- B12-B14: g1 = att(x_c, x_q2), g2 = att(x_c, qt) ----
    attn_pair(sc + OFF_XC, sc + OFF_XQ, tgt, 2, Wk, W2, sc, sm, 12);

    // ---- B15: per-batch fsm(g1), fsm(g2), score softmax, rank top-k ----
    if (bid < NBAT) {
        float* red = sm;
        float* ss = sm + 64;
        float g1v = fsm_dev(sc + OFF_H2 + (size_t)bid * 8192, W3 + 256, red);
        float g2v = fsm_dev(sc + OFF_H2 + 524288 + (size_t)bid * 8192, W3 + 384, red);
        float v = g1v + g2v;
        if (tid < 64) red[tid] = v;
        __syncthreads();
        for (int off = 32; off > 0; off >>= 1) {
            if (tid < off) red[tid] = fmaxf(red[tid], red[tid + off]);
            __syncthreads();
        }
        float m = red[0];
        __syncthreads();
        float e = 0.f;
        if (tid < 64) { e = expf(v - m); red[tid] = e; }
        __syncthreads();
        for (int off = 32; off > 0; off >>= 1) {
            if (tid < off) red[tid] += red[tid + off];
            __syncthreads();
        }
        float si = (tid < 64) ? e / red[0] : 0.f;
        __syncthreads();
        if (tid < 64) ss[tid] = si;
        __syncthreads();
        if (tid < 64) {
            int rank = 0;
            for (int j = 0; j < 64; j++) {
                float sj = ss[j];
                rank += (sj > si) || (sj == si && j < tid);
            }
            sc[OFF_SCORE + bid * 64 + tid] = si;
            if (rank < KSEL) ((int*)(sc + OFF_PERM))[bid * KSEL + rank] = tid;
        }
    }
    gsync(15);

    // ---- B16: outputs — blocks 0-63: A2 diag blocks; 64-127: x_out/batch/perm ----
    if (bid < NBAT) {
        float* Aws = sm;           // [64][65]
        float* Sp  = sm + 4160;    // [64][53]
        float* Ms  = sm + 7552;    // [64][53]
        int*   idx = (int*)(sm + 10944);
        const int* perm = (const int*)(sc + OFF_PERM);
        const float* Ab = sc + OFF_AW + (size_t)bid * 4096;
        for (int i = tid; i < 4096; i += NTHR) Aws[(i >> 6) * 65 + (i & 63)] = Ab[i];
        if (tid < KSEL) idx[tid] = perm[bid * KSEL + tid];
        __syncthreads();
        const float* Sb = sc + OFF_S + (size_t)bid * 4096;
        for (int i = tid; i < 64 * KSEL; i += NTHR) {
            int r = i / KSEL, j = i % KSEL;
            Sp[r * 53 + j] = Sb[r * 64 + idx[j]];
        }
        __syncthreads();
        for (int i = tid; i < 64 * KSEL; i += NTHR) {
            int r = i / KSEL, j = i % KSEL;
            float acc = 0.f;
            #pragma unroll 8
            for (int c = 0; c < 64; c++) acc += Aws[r * 65 + c] * Sp[c * 53 + j];
            Ms[r * 53 + j] = acc;
        }
        __syncthreads();
        for (int i = tid; i < KSEL * KSEL; i += NTHR) {
            int ii = i / KSEL, j = i % KSEL;
            float v;
            if (ii == j) v = 1.f;
            else {
                v = 0.f;
                #pragma unroll 8
                for (int r = 0; r < 64; r++) v += Sp[r * 53 + ii] * Ms[r * 53 + j];
            }
            long long gi = (long long)bid * KSEL + ii;
            out[O_A2 + gi * NKEEP + bid * KSEL + j] = v;
        }
    } else {
        int wb = bid - NBAT;
        const int* perm = (const int*)(sc + OFF_PERM);
        for (int t = wb * NTHR + tid; t < NKEEP * HDIM; t += NBAT * NTHR) {
            int j = t >> 7, k = t & 127;
            int b = j / KSEL;
            int pg = b * 64 + perm[j];
            out[t] = x[(size_t)pg * 128 + k] * sc[OFF_SCORE + pg];
            if (k == 0) {
                out[O_BAT + j]  = (float)b;
                out[O_PERM + j] = (float)pg;
            }
        }
    }
}

extern "C" void kernel_launch(void* const* d_in, const int* in_sizes, int n_in,
                              void* d_out, int out_size) {
    const float* x   = (const float*)d_in[0];
    const int*   ei  = (const int*)d_in[1];
    const float* ew  = (const float*)d_in[2];
    const float* tgt = (const float*)d_in[3];
    const float* Wk  = (const float*)d_in[5];
    const float* W1  = (const float*)d_in[6];
    const float* W2  = (const float*)d_in[7];
    const float* W3  = (const float*)d_in[8];
    const float* lW  = (const float*)d_in[9];
    mega<<<NBLK, NTHR>>>(x, ei, ew, tgt, Wk, W1, W2, W3, lW, (float*)d_out);
}